// round 6
// baseline (speedup 1.0000x reference)
#include <cuda_runtime.h>
#include <cstdint>

// ======== fixed problem dims ========
static constexpr int TT = 4096;
static constexpr int HH = 1024;
static constexpr int FF = 4096;
static constexpr int EE = 8;

// ======== device scratch ========
__device__ int   g_cnt[EE];
__device__ int   g_perm[EE * TT];
__device__ float g_gate[EE * TT];
__device__ float g_xr[(size_t)TT * HH];       // tf32-rounded x
__device__ float g_h[(size_t)EE * TT * FF];   // tf32-rounded intermediate

#define DEVI __device__ __forceinline__

DEVI uint32_t smem_u32(const void* p) {
    uint32_t a;
    asm("{ .reg .u64 t; cvta.to.shared.u64 t, %1; cvt.u32.u64 %0, t; }" : "=r"(a) : "l"(p));
    return a;
}

DEVI void ldsm4(uint32_t* r, uint32_t addr) {
    asm volatile("ldmatrix.sync.aligned.m8n8.x4.shared.b16 {%0,%1,%2,%3}, [%4];"
        : "=r"(r[0]), "=r"(r[1]), "=r"(r[2]), "=r"(r[3]) : "r"(addr));
}
DEVI void cvt4(uint32_t* r) {
#pragma unroll
    for (int i = 0; i < 4; i++) asm("cvt.rna.tf32.f32 %0, %0;" : "+r"(r[i]));
}
DEVI float rnd_tf32(float f) {
    uint32_t u;
    asm("cvt.rna.tf32.f32 %0, %1;" : "=r"(u) : "f"(f));
    return __uint_as_float(u);
}

DEVI void mma8(float* d, const uint32_t* a, uint32_t b0, uint32_t b1) {
    asm volatile(
        "mma.sync.aligned.m16n8k8.row.col.f32.tf32.tf32.f32 "
        "{%0,%1,%2,%3}, {%4,%5,%6,%7}, {%8,%9}, {%0,%1,%2,%3};"
        : "+f"(d[0]), "+f"(d[1]), "+f"(d[2]), "+f"(d[3])
        : "r"(a[0]), "r"(a[1]), "r"(a[2]), "r"(a[3]), "r"(b0), "r"(b1));
}

DEVI void cp16(uint32_t dst, const void* src) {
    asm volatile("cp.async.cg.shared.global [%0], [%1], 16;" :: "r"(dst), "l"(src) : "memory");
}
#define CP_COMMIT() asm volatile("cp.async.commit_group;" ::: "memory")
#define CP_WAIT1()  asm volatile("cp.async.wait_group 1;" ::: "memory")

DEVI float silu(float v) { return v / (1.f + __expf(-v)); }

// ======== kernel 0: zero counters ========
__global__ void moe_zero() {
    if (threadIdx.x < EE) g_cnt[threadIdx.x] = 0;
}

// ======== kernel 0b: pre-round x to tf32 ========
__global__ void __launch_bounds__(256) moe_round_x(const float* __restrict__ x) {
    int i = blockIdx.x * 256 + threadIdx.x;
    float4 v = ((const float4*)x)[i];
    v.x = rnd_tf32(v.x); v.y = rnd_tf32(v.y); v.z = rnd_tf32(v.z); v.w = rnd_tf32(v.w);
    ((float4*)g_xr)[i] = v;
}

// ======== kernel 1: router ========
__global__ void __launch_bounds__(128) moe_router(
    const float* __restrict__ x, const float* __restrict__ wr, float* __restrict__ logits)
{
    __shared__ float swr[EE * HH];
    for (int i = threadIdx.x; i < EE * HH; i += 128) {
        int col = i >> 3, e = i & 7;
        swr[i] = wr[e * HH + col];
    }
    __syncthreads();

    int nwarp = gridDim.x * 4;
    int warp  = blockIdx.x * 4 + (threadIdx.x >> 5);
    int lane  = threadIdx.x & 31;

    for (int t = warp; t < TT; t += nwarp) {
        float acc[EE];
#pragma unroll
        for (int e = 0; e < EE; e++) acc[e] = 0.f;
        const float4* xr = (const float4*)(x + (size_t)t * HH);
        for (int i = lane; i < HH / 4; i += 32) {
            float4 v = xr[i];
            int c = i * 4;
#pragma unroll
            for (int e = 0; e < EE; e++)
                acc[e] += v.x * swr[(c + 0) * 8 + e] + v.y * swr[(c + 1) * 8 + e]
                        + v.z * swr[(c + 2) * 8 + e] + v.w * swr[(c + 3) * 8 + e];
        }
#pragma unroll
        for (int e = 0; e < EE; e++) {
#pragma unroll
            for (int o = 16; o > 0; o >>= 1)
                acc[e] += __shfl_xor_sync(0xffffffffu, acc[e], o);
        }
        if (lane == 0) {
            float mx = acc[0];
#pragma unroll
            for (int e = 1; e < EE; e++) mx = fmaxf(mx, acc[e]);
            float p[EE];
#pragma unroll
            for (int e = 0; e < EE; e++) p[e] = __expf(acc[e] - mx);
            int e0 = 0;
#pragma unroll
            for (int e = 1; e < EE; e++) if (p[e] > p[e0]) e0 = e;
            int e1 = (e0 == 0) ? 1 : 0;
#pragma unroll
            for (int e = 0; e < EE; e++) if (e != e0 && p[e] > p[e1]) e1 = e;
            float ws = p[e0] + p[e1];
            float w0 = p[e0] / ws, w1v = p[e1] / ws;
#pragma unroll
            for (int e = 0; e < EE; e++) logits[(size_t)t * EE + e] = acc[e];
            int q0 = atomicAdd(&g_cnt[e0], 1);
            g_perm[e0 * TT + q0] = t; g_gate[e0 * TT + q0] = w0;
            int q1 = atomicAdd(&g_cnt[e1], 1);
            g_perm[e1 * TT + q1] = t; g_gate[e1 * TT + q1] = w1v;
        }
    }
}

// ======== GEMM1: h = silu(X w1^T) * (X w3^T) ========
// 256 threads, block tile M=128 x N=64 dual-B. Warps 2M x 4N, warp 64x16 dual.
// 3-stage cp.async; fragment-pipelined inner loop (rotating A, double-buffered B).
static constexpr int G1_STAGE = 2 * 16384;            // A(128x32) + B(128x32)
static constexpr int SMEM1 = 512 + 3 * G1_STAGE + 128;

DEVI void g1_load(uint32_t st, int kc, int tid, const int* s_tok,
                  const float* xr, const float* w1r, const float* w3r)
{
#pragma unroll
    for (int p = 0; p < 8; p++) {
        int within = tid + 256 * (p & 3);
        int row = within >> 3, ch = within & 7;
        uint32_t dst = st + (uint32_t)(p >> 2) * 16384u
                     + (uint32_t)row * 128u + ((uint32_t)(ch ^ (row & 7)) << 4);
        const float* src;
        if (p < 4) src = xr + (size_t)s_tok[row] * HH + kc * 32 + ch * 4;
        else       src = (row < 64 ? w1r + (size_t)row * HH
                                   : w3r + (size_t)(row - 64) * HH) + kc * 32 + ch * 4;
        cp16(dst, src);
    }
}

__global__ void __launch_bounds__(256, 2) moe_gemm1(
    const float* __restrict__ w1, const float* __restrict__ w3)
{
    int e   = blockIdx.z;
    int cnt = g_cnt[e];
    int m0  = blockIdx.x * 128;
    if (m0 >= cnt) return;
    int f0  = blockIdx.y * 64;

    extern __shared__ char sm[];
    int* s_tok = (int*)sm;
    uint32_t sb = (smem_u32(sm) + 512u + 127u) & ~127u;   // 128B-aligned stage base

    int tid = threadIdx.x, wid = tid >> 5, lane = tid & 31;
    int wm = wid & 1, wn = wid >> 1;

    if (tid < 128) {
        int slot = m0 + tid;
        s_tok[tid] = g_perm[e * TT + (slot < cnt ? slot : 0)];
    }
    __syncthreads();

    const float* w1r = w1 + (size_t)e * FF * HH + (size_t)f0 * HH;
    const float* w3r = w3 + (size_t)e * FF * HH + (size_t)f0 * HH;

    g1_load(sb, 0, tid, s_tok, g_xr, w1r, w3r);
    CP_COMMIT();
    g1_load(sb + G1_STAGE, 1, tid, s_tok, g_xr, w1r, w3r);
    CP_COMMIT();

    // per-warp fragment address offsets (swizzle folded; k-step applied via XOR imm)
    uint32_t hiA   = (uint32_t)(lane >> 4);
    uint32_t cselB = (uint32_t)((lane >> 3) & 1);
    uint32_t aoff[4];
#pragma unroll
    for (int mi = 0; mi < 4; mi++) {
        int r = wm * 64 + mi * 16 + (lane & 15);
        aoff[mi] = (uint32_t)r * 128u + ((hiA ^ (uint32_t)(r & 7)) << 4);
    }
    int nb1 = wn * 16 + (lane & 7) + ((lane >> 4) << 3);
    int nb3 = nb1 + 64;
    uint32_t boff1 = (uint32_t)nb1 * 128u + ((cselB ^ (uint32_t)(nb1 & 7)) << 4);
    uint32_t boff3 = (uint32_t)nb3 * 128u + ((cselB ^ (uint32_t)(nb3 & 7)) << 4);

    float c1[4][2][4], c3[4][2][4];
#pragma unroll
    for (int i = 0; i < 4; i++)
#pragma unroll
        for (int j = 0; j < 2; j++)
#pragma unroll
            for (int k = 0; k < 4; k++) { c1[i][j][k] = 0.f; c3[i][j][k] = 0.f; }

    int s = 0;
    for (int kc = 0; kc < HH / 32; kc++) {
        CP_WAIT1();
        __syncthreads();
        // issue next-stage loads FIRST (overlap DRAM with MMA below)
        if (kc + 2 < HH / 32) {
            int s2 = s + 2; if (s2 >= 3) s2 -= 3;
            g1_load(sb + (uint32_t)s2 * G1_STAGE, kc + 2, tid, s_tok, g_xr, w1r, w3r);
        }
        CP_COMMIT();

        uint32_t As = sb + (uint32_t)s * G1_STAGE;
        uint32_t Bs = As + 16384u;
        uint32_t adA[4];
#pragma unroll
        for (int mi = 0; mi < 4; mi++) adA[mi] = As + aoff[mi];
        uint32_t adB1 = Bs + boff1, adB3 = Bs + boff3;

        uint32_t a[4][4], b1f[2][4], b3f[2][4];
        ldsm4(b1f[0], adB1);
        ldsm4(b3f[0], adB3);
#pragma unroll
        for (int mi = 0; mi < 4; mi++) ldsm4(a[mi], adA[mi]);

#pragma unroll
        for (int ks = 0; ks < 4; ks++) {
            const int p = ks & 1;
            const uint32_t xn = (uint32_t)(ks + 1) * 0x20u;
            if (ks < 3) { ldsm4(b1f[p ^ 1], adB1 ^ xn); ldsm4(b3f[p ^ 1], adB3 ^ xn); }
            cvt4(b1f[p]); cvt4(b3f[p]);
#pragma unroll
            for (int mi = 0; mi < 4; mi++) {
                mma8(c1[mi][0], a[mi], b1f[p][0], b1f[p][1]);
                mma8(c1[mi][1], a[mi], b1f[p][2], b1f[p][3]);
                mma8(c3[mi][0], a[mi], b3f[p][0], b3f[p][1]);
                mma8(c3[mi][1], a[mi], b3f[p][2], b3f[p][3]);
                if (ks < 3) ldsm4(a[mi], adA[mi] ^ xn);   // rotate-refresh A
            }
        }
        if (++s == 3) s = 0;
    }

    // epilogue: silu(p1)*p3, rounded to tf32 -> g_h
    size_t hrow_base = (size_t)e * TT + m0;
#pragma unroll
    for (int mi = 0; mi < 4; mi++) {
        int lr = wm * 64 + mi * 16 + (lane >> 2);
#pragma unroll
        for (int ni = 0; ni < 2; ni++) {
            int lc = wn * 16 + ni * 8 + (lane & 3) * 2;
            float v0 = rnd_tf32(silu(c1[mi][ni][0]) * c3[mi][ni][0]);
            float v1 = rnd_tf32(silu(c1[mi][ni][1]) * c3[mi][ni][1]);
            float v2 = rnd_tf32(silu(c1[mi][ni][2]) * c3[mi][ni][2]);
            float v3 = rnd_tf32(silu(c1[mi][ni][3]) * c3[mi][ni][3]);
            *(float2*)&g_h[(hrow_base + lr)     * FF + f0 + lc] = make_float2(v0, v1);
            *(float2*)&g_h[(hrow_base + lr + 8) * FF + f0 + lc] = make_float2(v2, v3);
        }
    }
}

// ======== GEMM2: out += gate * (h w2^T) ========
// 256 threads, block 128x128, warps 2M x 4N, warp 64x32; same fragment pipeline.
static constexpr int G2_STAGE = 2 * 16384;
static constexpr int SMEM2 = 1024 + 3 * G2_STAGE + 128;

DEVI void g2_load(uint32_t st, int kc, int tid, const float* ha, const float* w2r)
{
#pragma unroll
    for (int p = 0; p < 8; p++) {
        int within = tid + 256 * (p & 3);
        int row = within >> 3, ch = within & 7;
        uint32_t dst = st + (uint32_t)(p >> 2) * 16384u
                     + (uint32_t)row * 128u + ((uint32_t)(ch ^ (row & 7)) << 4);
        const float* src = (p < 4) ? ha + (size_t)row * FF + kc * 32 + ch * 4
                                   : w2r + (size_t)row * FF + kc * 32 + ch * 4;
        cp16(dst, src);
    }
}

__global__ void __launch_bounds__(256, 2) moe_gemm2(
    const float* __restrict__ w2, float* __restrict__ out)
{
    int e   = blockIdx.z;
    int cnt = g_cnt[e];
    int m0  = blockIdx.x * 128;
    if (m0 >= cnt) return;
    int h0  = blockIdx.y * 128;

    extern __shared__ char sm[];
    int*   s_tok  = (int*)sm;
    float* s_gate = (float*)(sm + 512);
    uint32_t sb = (smem_u32(sm) + 1024u + 127u) & ~127u;

    int tid = threadIdx.x, wid = tid >> 5, lane = tid & 31;
    int wm = wid & 1, wn = wid >> 1;

    if (tid < 128) {
        int slot = m0 + tid;
        int idx  = e * TT + (slot < cnt ? slot : 0);
        s_tok[tid]  = g_perm[idx];
        s_gate[tid] = g_gate[idx];
    }
    __syncthreads();

    const float* ha  = &g_h[((size_t)e * TT + m0) * FF];
    const float* w2r = w2 + (size_t)e * HH * FF + (size_t)h0 * FF;

    g2_load(sb, 0, tid, ha, w2r);
    CP_COMMIT();
    g2_load(sb + G2_STAGE, 1, tid, ha, w2r);
    CP_COMMIT();

    uint32_t hiA   = (uint32_t)(lane >> 4);
    uint32_t cselB = (uint32_t)((lane >> 3) & 1);
    uint32_t aoff[4], boff[2];
#pragma unroll
    for (int mi = 0; mi < 4; mi++) {
        int r = wm * 64 + mi * 16 + (lane & 15);
        aoff[mi] = (uint32_t)r * 128u + ((hiA ^ (uint32_t)(r & 7)) << 4);
    }
#pragma unroll
    for (int p = 0; p < 2; p++) {
        int n = wn * 32 + p * 16 + (lane & 7) + ((lane >> 4) << 3);
        boff[p] = (uint32_t)n * 128u + ((cselB ^ (uint32_t)(n & 7)) << 4);
    }

    float cc[4][4][4];
#pragma unroll
    for (int i = 0; i < 4; i++)
#pragma unroll
        for (int j = 0; j < 4; j++)
#pragma unroll
            for (int k = 0; k < 4; k++) cc[i][j][k] = 0.f;

    int s = 0;
    for (int kc = 0; kc < FF / 32; kc++) {
        CP_WAIT1();
        __syncthreads();
        if (kc + 2 < FF / 32) {
            int s2 = s + 2; if (s2 >= 3) s2 -= 3;
            g2_load(sb + (uint32_t)s2 * G2_STAGE, kc + 2, tid, ha, w2r);
        }
        CP_COMMIT();

        uint32_t As = sb + (uint32_t)s * G2_STAGE;
        uint32_t Bs = As + 16384u;
        uint32_t adA[4];
#pragma unroll
        for (int mi = 0; mi < 4; mi++) adA[mi] = As + aoff[mi];
        uint32_t adB0 = Bs + boff[0], adB1 = Bs + boff[1];

        uint32_t a[4][4], bb[2][2][4];
        ldsm4(bb[0][0], adB0);
        ldsm4(bb[0][1], adB1);
#pragma unroll
        for (int mi = 0; mi < 4; mi++) ldsm4(a[mi], adA[mi]);

#pragma unroll
        for (int ks = 0; ks < 4; ks++) {
            const int p = ks & 1;
            const uint32_t xn = (uint32_t)(ks + 1) * 0x20u;
            if (ks < 3) { ldsm4(bb[p ^ 1][0], adB0 ^ xn); ldsm4(bb[p ^ 1][1], adB1 ^ xn); }
            cvt4(bb[p][0]); cvt4(bb[p][1]);
#pragma unroll
            for (int mi = 0; mi < 4; mi++) {
                mma8(cc[mi][0], a[mi], bb[p][0][0], bb[p][0][1]);
                mma8(cc[mi][1], a[mi], bb[p][0][2], bb[p][0][3]);
                mma8(cc[mi][2], a[mi], bb[p][1][0], bb[p][1][1]);
                mma8(cc[mi][3], a[mi], bb[p][1][2], bb[p][1][3]);
                if (ks < 3) ldsm4(a[mi], adA[mi] ^ xn);
            }
        }
        if (++s == 3) s = 0;
    }

    // epilogue: scatter-add with gate weights
#pragma unroll
    for (int mi = 0; mi < 4; mi++) {
        int lr0 = wm * 64 + mi * 16 + (lane >> 2);
        int lr1 = lr0 + 8;
        bool v0 = (m0 + lr0) < cnt, v1 = (m0 + lr1) < cnt;
        int   t0 = s_tok[lr0],  t1 = s_tok[lr1];
        float gg0 = s_gate[lr0], gg1 = s_gate[lr1];
        float* o0 = out + (size_t)t0 * HH + h0;
        float* o1 = out + (size_t)t1 * HH + h0;
#pragma unroll
        for (int ni = 0; ni < 4; ni++) {
            int lc = wn * 32 + ni * 8 + (lane & 3) * 2;
            if (v0) {
                atomicAdd(&o0[lc],     gg0 * cc[mi][ni][0]);
                atomicAdd(&o0[lc + 1], gg0 * cc[mi][ni][1]);
            }
            if (v1) {
                atomicAdd(&o1[lc],     gg1 * cc[mi][ni][2]);
                atomicAdd(&o1[lc + 1], gg1 * cc[mi][ni][3]);
            }
        }
    }
}

// ======== launch ========
extern "C" void kernel_launch(void* const* d_in, const int* in_sizes, int n_in,
                              void* d_out, int out_size)
{
    (void)in_sizes; (void)n_in; (void)out_size;
    const float* x  = (const float*)d_in[0];
    const float* wr = (const float*)d_in[1];
    const float* w1 = (const float*)d_in[2];
    const float* w2 = (const float*)d_in[3];
    const float* w3 = (const float*)d_in[4];
    float* out    = (float*)d_out;
    float* logits = out + (size_t)TT * HH;

    cudaFuncSetAttribute(moe_gemm1, cudaFuncAttributeMaxDynamicSharedMemorySize, SMEM1);
    cudaFuncSetAttribute(moe_gemm2, cudaFuncAttributeMaxDynamicSharedMemorySize, SMEM2);

    cudaMemsetAsync(out, 0, (size_t)TT * HH * sizeof(float));
    moe_zero<<<1, 32>>>();
    moe_round_x<<<TT * HH / 1024, 256>>>(x);
    moe_router<<<64, 128>>>(x, wr, logits);
    moe_gemm1<<<dim3(32, 64, EE), 256, SMEM1>>>(w1, w3);
    moe_gemm2<<<dim3(32, 8, EE), 256, SMEM2>>>(w2, out);
}